// round 5
// baseline (speedup 1.0000x reference)
#include <cuda_runtime.h>

// Shapes: re, gt are (B=32, C=10, H=192, W=320) float32, contiguous.
#define NB     32
#define NC     10
#define HW4    15360                  // (192*320)/4 float4 groups per channel
#define N4     (NB*HW4)               // 491520 groups total
#define BLK    256
#define GRID   (N4/BLK)               // 1920 blocks, exactly 1 group per thread
#define NACC   11

// [0]=nv [1]=num_pos [2]=pos_term [3]=neg_term [4]=S_pos
// [5]=S_len1 [6]=S_len2 [7]=S_trig1 [8]=S_trig2 [9]=S_const [10]=S_h
__device__ float g_part[NACC][GRID];
__device__ unsigned int g_count = 0;   // reset by last block each launch

__device__ __forceinline__ float sl1(float d) {
    float ad = fabsf(d);
    return ad < 1.0f ? 0.5f * d * d : ad - 0.5f;
}

__device__ __forceinline__ float c4(const float4& v, int j) {
    return j == 0 ? v.x : (j == 1 ? v.y : (j == 2 ? v.z : v.w));
}

__global__ void __launch_bounds__(BLK)
loss_kernel(const float* __restrict__ re, const float* __restrict__ gt,
            float* __restrict__ out) {
    float acc[NACC];
#pragma unroll
    for (int k = 0; k < NACC; k++) acc[k] = 0.0f;

    const float4* __restrict__ re4 = (const float4*)re;
    const float4* __restrict__ gt4 = (const float4*)gt;

    const int i   = blockIdx.x * BLK + threadIdx.x;   // group index, < N4
    const int b   = i / HW4;
    const int hw4 = i - b * HW4;
    const int bs  = b * (NC * HW4) + hw4;             // float4 idx of (b,0,hw)

    const float4 G = gt4[bs];
    const float4 R = re4[bs];

    bool mv[4];
    bool any = false;
#pragma unroll
    for (int j = 0; j < 4; j++) {
        float g = c4(G, j);
        float r = c4(R, j);
        bool m = (g == 1.0f);
        mv[j] = m;
        any |= m;
        if (m) acc[0] += 1.0f;
        if (g >= 0.0f) {
            float safe = fminf(fmaxf(r, 1e-6f), 1.0f - 1e-6f);
            if (g >= 0.1f) {                          // FOCAL_THR
                acc[1] += 1.0f;
                float d = g - r;
                acc[2] -= d * d * __logf(safe + 6e-8f);
            } else {
                float om  = 1.0f - g;
                float om2 = om * om;
                acc[3] -= r * r * __logf(1.0f + 6e-8f - safe) * om2 * om2;
            }
        }
    }

    if (any) {
        // Issue ALL 18 channel loads in one window (MLP=18); compute after.
        float4 R1 = re4[bs + 1*HW4], G1 = gt4[bs + 1*HW4];
        float4 R2 = re4[bs + 2*HW4], G2 = gt4[bs + 2*HW4];
        float4 R3 = re4[bs + 3*HW4], G3 = gt4[bs + 3*HW4];
        float4 R4 = re4[bs + 4*HW4], G4 = gt4[bs + 4*HW4];
        float4 R5 = re4[bs + 5*HW4], G5 = gt4[bs + 5*HW4];
        float4 R6 = re4[bs + 6*HW4], G6 = gt4[bs + 6*HW4];
        float4 R7 = re4[bs + 7*HW4], G7 = gt4[bs + 7*HW4];
        float4 R8 = re4[bs + 8*HW4], G8 = gt4[bs + 8*HW4];
        float4 R9 = re4[bs + 9*HW4], G9 = gt4[bs + 9*HW4];

#pragma unroll
        for (int j = 0; j < 4; j++) {
            if (!mv[j]) continue;
            acc[4] += sl1(c4(R1,j) - c4(G1,j)) + sl1(c4(R2,j) - c4(G2,j));

            float r3 = c4(R3,j), g3 = c4(G3,j);
            float r6 = c4(R6,j), g6 = c4(G6,j);
            acc[5] += sl1(r3 - g3) + sl1(r6 - g6);
            acc[6] += sl1(r3 - g6) + sl1(r6 - g3);

            float r4 = c4(R4,j), g4 = c4(G4,j);
            float r5 = c4(R5,j), g5 = c4(G5,j);
            float r7 = c4(R7,j), g7 = c4(G7,j);
            float r8 = c4(R8,j), g8 = c4(G8,j);
            float d44 = r4 - g4, d77 = r7 - g7;
            float d55 = r5 - g5, d88 = r8 - g8;
            acc[7] += d44*d44 + d77*d77 + d55*d55 + d88*d88;
            float d47 = r4 - g7, d74 = r7 - g4;
            float d58 = r5 - g8, d85 = r8 - g5;
            acc[8] += d47*d47 + d74*d74 + d58*d58 + d85*d85;
            float c1 = 1.0f - r5*r5 - r4*r4;
            float c2 = 1.0f - r8*r8 - r7*r7;
            acc[9] += c1*c1 + c2*c2;

            acc[10] += sl1(c4(R9,j) - c4(G9,j));
        }
    }

    // Block reduction: warp shuffle -> shared -> per-block partial slot.
    __shared__ float sh[BLK/32][NACC];
    const int lane = threadIdx.x & 31;
    const int warp = threadIdx.x >> 5;
#pragma unroll
    for (int k = 0; k < NACC; k++) {
        float v = acc[k];
#pragma unroll
        for (int o = 16; o > 0; o >>= 1)
            v += __shfl_down_sync(0xffffffffu, v, o);
        if (lane == 0) sh[warp][k] = v;
    }
    __syncthreads();
    if (threadIdx.x < NACC) {
        float v = 0.0f;
#pragma unroll
        for (int w = 0; w < BLK/32; w++) v += sh[w][threadIdx.x];
        g_part[threadIdx.x][blockIdx.x] = v;
    }

    // Last-block-done: the final block to arrive reduces all partials.
    __shared__ bool is_last;
    __threadfence();
    __syncthreads();
    if (threadIdx.x == 0) {
        unsigned int old = atomicAdd(&g_count, 1u);
        is_last = (old == GRID - 1);
    }
    __syncthreads();
    if (!is_last) return;

    __threadfence();   // ensure we see every block's partials

    // 8 warps reduce 11 accumulators: warp w handles k=w, warps 0-2 also k=w+8.
    __shared__ float tot[NACC];
#pragma unroll
    for (int pass = 0; pass < 2; pass++) {
        int k = warp + pass * 8;
        if (k < NACC) {
            float v = 0.0f;
            for (int j = lane; j < GRID; j += 32) v += g_part[k][j];
#pragma unroll
            for (int o = 16; o > 0; o >>= 1)
                v += __shfl_down_sync(0xffffffffu, v, o);
            if (lane == 0) tot[k] = v;
        }
    }
    __syncthreads();

    if (threadIdx.x == 0) {
        g_count = 0;   // reset for next graph replay (deterministic)

        float nv       = tot[0];
        float num_pos  = tot[1];
        float pos_term = tot[2];
        float neg_term = tot[3];

        float focal = (num_pos == 0.0f) ? neg_term
                                        : (pos_term + neg_term) / num_pos;
        float inv2nv = 1.0f / (2.0f * nv);
        float invnv  = 1.0f / nv;

        float confidence_loss = 1.0f * focal;             // CONF_W
        float pos_loss   = 1.0f * tot[4] * inv2nv;        // POS_W
        float len_v1     = 0.1f * tot[5] * inv2nv;        // LEN_W
        float len_v2     = 0.1f * tot[6] * inv2nv;
        float trig_v1    = 1.0f * tot[7] * inv2nv;        // TRIG_W
        float trig_v2    = 1.0f * tot[8] * inv2nv;
        float const_loss = 0.5f * tot[9] * invnv;         // CONST_W
        float height     = 0.1f * tot[10] * invnv;        // LEN_W

        float dims = fminf(len_v1 + trig_v1, len_v2 + trig_v2) + height;
        out[0] = confidence_loss + pos_loss + dims + const_loss;
    }
}

extern "C" void kernel_launch(void* const* d_in, const int* in_sizes, int n_in,
                              void* d_out, int out_size) {
    const float* re = (const float*)d_in[0];
    const float* gt = (const float*)d_in[1];
    float* out = (float*)d_out;

    loss_kernel<<<GRID, BLK>>>(re, gt, out);
}

// round 6
// speedup vs baseline: 1.1542x; 1.1542x over previous
#include <cuda_runtime.h>

// Shapes: re, gt are (B=32, C=10, H=192, W=320) float32, contiguous.
#define NB     32
#define NC     10
#define HW4    15360                  // (192*320)/4 float4 groups per channel
#define N4     (NB*HW4)               // 491520 groups total
#define BLK    256
#define GPT    2                      // groups per thread
#define GRID   (N4/(BLK*GPT))         // 960 blocks
#define STRIDE (GRID*BLK)             // 245760
#define NACC   7

// [0]=nv [1]=num_pos [2]=pos_term [3]=neg_term
// [4]=A (pos+height+const, /nv)  [5]=B (len1+trig1, /nv)  [6]=C (len2+trig2, /nv)
__device__ float g_part[NACC][GRID];
__device__ unsigned int g_count = 0;   // reset by last block each launch

__device__ __forceinline__ float sl1(float d) {
    float ad = fabsf(d);
    return ad < 1.0f ? 0.5f * d * d : ad - 0.5f;
}

__device__ __forceinline__ float c4(const float4& v, int j) {
    return j == 0 ? v.x : (j == 1 ? v.y : (j == 2 ? v.z : v.w));
}

__global__ void __launch_bounds__(BLK, 4)
loss_kernel(const float* __restrict__ re, const float* __restrict__ gt,
            float* __restrict__ out) {
    float acc[NACC];
#pragma unroll
    for (int k = 0; k < NACC; k++) acc[k] = 0.0f;

    const float4* __restrict__ re4 = (const float4*)re;
    const float4* __restrict__ gt4 = (const float4*)gt;

    const int t = blockIdx.x * BLK + threadIdx.x;

#pragma unroll
    for (int it = 0; it < GPT; it++) {
        const int i   = t + it * STRIDE;
        const int b   = i / HW4;
        const int hw4 = i - b * HW4;
        const int bs  = b * (NC * HW4) + hw4;   // float4 idx of (b,0,hw)

        const float4 G = gt4[bs];
        const float4 R = re4[bs];

        bool mv[4];
        bool any = false;
#pragma unroll
        for (int j = 0; j < 4; j++) {
            float g = c4(G, j);
            float r = c4(R, j);
            bool m = (g == 1.0f);
            mv[j] = m;
            any |= m;
            if (m) acc[0] += 1.0f;
            if (g >= 0.0f) {
                float safe = fminf(fmaxf(r, 1e-6f), 1.0f - 1e-6f);
                if (g >= 0.1f) {                      // FOCAL_THR
                    acc[1] += 1.0f;
                    float d = g - r;
                    acc[2] -= d * d * __logf(safe + 6e-8f);
                } else {
                    float om  = 1.0f - g;
                    float om2 = om * om;
                    acc[3] -= r * r * __logf(1.0f + 6e-8f - safe) * om2 * om2;
                }
            }
        }

        if (any) {
            // Window 1: channels 1,2,3,6,9 (pos / length / height)
            {
                float4 R1 = re4[bs + 1*HW4], G1 = gt4[bs + 1*HW4];
                float4 R2 = re4[bs + 2*HW4], G2 = gt4[bs + 2*HW4];
                float4 R3 = re4[bs + 3*HW4], G3 = gt4[bs + 3*HW4];
                float4 R6 = re4[bs + 6*HW4], G6 = gt4[bs + 6*HW4];
                float4 R9 = re4[bs + 9*HW4], G9 = gt4[bs + 9*HW4];
#pragma unroll
                for (int j = 0; j < 4; j++) {
                    if (!mv[j]) continue;
                    // pos (POS_W=1, /2nv -> 0.5) + height (LEN_W=0.1, /nv)
                    acc[4] += 0.5f * (sl1(c4(R1,j) - c4(G1,j))
                                    + sl1(c4(R2,j) - c4(G2,j)))
                            + 0.1f * sl1(c4(R9,j) - c4(G9,j));
                    // length (LEN_W=0.1, /2nv -> 0.05)
                    float r3 = c4(R3,j), g3 = c4(G3,j);
                    float r6 = c4(R6,j), g6 = c4(G6,j);
                    acc[5] += 0.05f * (sl1(r3 - g3) + sl1(r6 - g6));
                    acc[6] += 0.05f * (sl1(r3 - g6) + sl1(r6 - g3));
                }
            }
            // Window 2: channels 4,5,7,8 (trig / const)
            {
                float4 R4 = re4[bs + 4*HW4], G4 = gt4[bs + 4*HW4];
                float4 R5 = re4[bs + 5*HW4], G5 = gt4[bs + 5*HW4];
                float4 R7 = re4[bs + 7*HW4], G7 = gt4[bs + 7*HW4];
                float4 R8 = re4[bs + 8*HW4], G8 = gt4[bs + 8*HW4];
#pragma unroll
                for (int j = 0; j < 4; j++) {
                    if (!mv[j]) continue;
                    float r4 = c4(R4,j), g4 = c4(G4,j);
                    float r5 = c4(R5,j), g5 = c4(G5,j);
                    float r7 = c4(R7,j), g7 = c4(G7,j);
                    float r8 = c4(R8,j), g8 = c4(G8,j);
                    float d44 = r4 - g4, d77 = r7 - g7;
                    float d55 = r5 - g5, d88 = r8 - g8;
                    // trig (TRIG_W=1, /2nv -> 0.5)
                    acc[5] += 0.5f * (d44*d44 + d77*d77 + d55*d55 + d88*d88);
                    float d47 = r4 - g7, d74 = r7 - g4;
                    float d58 = r5 - g8, d85 = r8 - g5;
                    acc[6] += 0.5f * (d47*d47 + d74*d74 + d58*d58 + d85*d85);
                    // const (CONST_W=0.5, /nv)
                    float c1 = 1.0f - r5*r5 - r4*r4;
                    float c2 = 1.0f - r8*r8 - r7*r7;
                    acc[4] += 0.5f * (c1*c1 + c2*c2);
                }
            }
        }
    }

    // Block reduction: warp shuffle -> shared -> per-block partial slot.
    __shared__ float sh[BLK/32][NACC];
    const int lane = threadIdx.x & 31;
    const int warp = threadIdx.x >> 5;
#pragma unroll
    for (int k = 0; k < NACC; k++) {
        float v = acc[k];
#pragma unroll
        for (int o = 16; o > 0; o >>= 1)
            v += __shfl_down_sync(0xffffffffu, v, o);
        if (lane == 0) sh[warp][k] = v;
    }
    __syncthreads();
    if (threadIdx.x < NACC) {
        float v = 0.0f;
#pragma unroll
        for (int w = 0; w < BLK/32; w++) v += sh[w][threadIdx.x];
        g_part[threadIdx.x][blockIdx.x] = v;
    }

    // Last-block-done: the final block to arrive reduces all partials.
    __shared__ bool is_last;
    __threadfence();
    __syncthreads();
    if (threadIdx.x == 0) {
        unsigned int old = atomicAdd(&g_count, 1u);
        is_last = (old == GRID - 1);
    }
    __syncthreads();
    if (!is_last) return;

    __threadfence();   // ensure we see every block's partials

    // 7 warps reduce the 7 accumulators over all 960 block partials.
    __shared__ float tot[NACC];
    if (warp < NACC) {
        float v = 0.0f;
        for (int j = lane; j < GRID; j += 32) v += g_part[warp][j];
#pragma unroll
        for (int o = 16; o > 0; o >>= 1)
            v += __shfl_down_sync(0xffffffffu, v, o);
        if (lane == 0) tot[warp] = v;
    }
    __syncthreads();

    if (threadIdx.x == 0) {
        g_count = 0;   // reset for next graph replay

        float nv       = tot[0];
        float num_pos  = tot[1];
        float pos_term = tot[2];
        float neg_term = tot[3];

        float focal = (num_pos == 0.0f) ? neg_term
                                        : (pos_term + neg_term) / num_pos;
        float invnv = 1.0f / nv;
        out[0] = focal + (tot[4] + fminf(tot[5], tot[6])) * invnv;
    }
}

extern "C" void kernel_launch(void* const* d_in, const int* in_sizes, int n_in,
                              void* d_out, int out_size) {
    const float* re = (const float*)d_in[0];
    const float* gt = (const float*)d_in[1];
    float* out = (float*)d_out;

    loss_kernel<<<GRID, BLK>>>(re, gt, out);
}

// round 7
// speedup vs baseline: 1.2369x; 1.0716x over previous
#include <cuda_runtime.h>

// Shapes: re, gt are (B=32, C=10, H=192, W=320) float32, contiguous.
#define NB     32
#define NC     10
#define HW4    15360                  // (192*320)/4 float4 groups per channel
#define N4     (NB*HW4)               // 491520 groups total
#define BLK    256
#define GRID   (N4/BLK)               // 1920 blocks, 1 group per thread
#define NACC   6
#define EPSF   6e-8f

// [0]=nv [1]=num_pos [2]=focal_sum (pos+neg terms)
// [3]=A (pos+height+const, /nv) [4]=B (len1+trig1, /nv) [5]=C (len2+trig2, /nv)
__device__ float g_part[NACC][GRID];
__device__ unsigned int g_count = 0;   // reset by last block each launch

__device__ __forceinline__ float sl1(float d) {
    float ad = fabsf(d);
    float q  = 0.5f * d * d;
    return ad < 1.0f ? q : ad - 0.5f;
}

__device__ __forceinline__ float c4(const float4& v, int j) {
    return j == 0 ? v.x : (j == 1 ? v.y : (j == 2 ? v.z : v.w));
}

__global__ void __launch_bounds__(BLK, 4)
loss_kernel(const float* __restrict__ re, const float* __restrict__ gt,
            float* __restrict__ out) {
    float a_nv = 0.f, a_np = 0.f, a_f = 0.f, a_A = 0.f, a_B = 0.f, a_C = 0.f;

    const float4* __restrict__ re4 = (const float4*)re;
    const float4* __restrict__ gt4 = (const float4*)gt;

    const int i   = blockIdx.x * BLK + threadIdx.x;   // group index, < N4
    const int b   = i / HW4;
    const int hw4 = i - b * HW4;
    const int bs  = b * (NC * HW4) + hw4;             // float4 idx of (b,0,hw)

    // Unconditional loads: all 20 streams, no control dependency.
    const float4 G0 = gt4[bs        ], R0 = re4[bs        ];
    const float4 G1 = gt4[bs + 1*HW4], R1 = re4[bs + 1*HW4];
    const float4 G2 = gt4[bs + 2*HW4], R2 = re4[bs + 2*HW4];
    const float4 G3 = gt4[bs + 3*HW4], R3 = re4[bs + 3*HW4];
    const float4 G4 = gt4[bs + 4*HW4], R4 = re4[bs + 4*HW4];
    const float4 G5 = gt4[bs + 5*HW4], R5 = re4[bs + 5*HW4];
    const float4 G6 = gt4[bs + 6*HW4], R6 = re4[bs + 6*HW4];
    const float4 G7 = gt4[bs + 7*HW4], R7 = re4[bs + 7*HW4];
    const float4 G8 = gt4[bs + 8*HW4], R8 = re4[bs + 8*HW4];
    const float4 G9 = gt4[bs + 9*HW4], R9 = re4[bs + 9*HW4];

#pragma unroll
    for (int j = 0; j < 4; j++) {
        const float g = c4(G0, j);
        const float r = c4(R0, j);

        // ---- focal (branchless, single log) ----
        const bool  m0  = (g >= 0.0f);
        const bool  pos = (g >= 0.1f);              // implies m0
        const float safe = fminf(fmaxf(r, 1e-6f), 1.0f - 1e-6f);
        const float larg = pos ? (safe + EPSF) : (1.0f + EPSF - safe);
        const float lg   = __logf(larg);            // larg > 0 always
        const float d0   = g - r;
        const float om   = 1.0f - g;
        const float om2  = om * om;
        float w = pos ? (d0 * d0) : (r * r * (om2 * om2));
        if (!m0) w = 0.0f;
        a_f -= w * lg;
        if (pos) a_np += 1.0f;

        // ---- mv-masked terms ----
        const float mvf = (g == 1.0f) ? 1.0f : 0.0f;
        a_nv += mvf;

        // pos (0.5 = POS_W/2) + height (0.1 = LEN_W) + const (0.5 = CONST_W)
        const float r4v = c4(R4,j), g4v = c4(G4,j);
        const float r5v = c4(R5,j), g5v = c4(G5,j);
        const float r7v = c4(R7,j), g7v = c4(G7,j);
        const float r8v = c4(R8,j), g8v = c4(G8,j);
        const float c1 = 1.0f - r5v*r5v - r4v*r4v;
        const float c2 = 1.0f - r8v*r8v - r7v*r7v;
        const float tA = 0.5f * (sl1(c4(R1,j) - c4(G1,j))
                               + sl1(c4(R2,j) - c4(G2,j)))
                       + 0.1f * sl1(c4(R9,j) - c4(G9,j))
                       + 0.5f * (c1*c1 + c2*c2);
        a_A += mvf * tA;

        // variant sums (len: 0.05 = LEN_W/2, trig: 0.5 = TRIG_W/2)
        const float r3v = c4(R3,j), g3v = c4(G3,j);
        const float r6v = c4(R6,j), g6v = c4(G6,j);
        const float d44 = r4v - g4v, d77 = r7v - g7v;
        const float d55 = r5v - g5v, d88 = r8v - g8v;
        const float tB = 0.05f * (sl1(r3v - g3v) + sl1(r6v - g6v))
                       + 0.5f  * (d44*d44 + d77*d77 + d55*d55 + d88*d88);
        a_B += mvf * tB;

        const float d47 = r4v - g7v, d74 = r7v - g4v;
        const float d58 = r5v - g8v, d85 = r8v - g5v;
        const float tC = 0.05f * (sl1(r3v - g6v) + sl1(r6v - g3v))
                       + 0.5f  * (d47*d47 + d74*d74 + d58*d58 + d85*d85);
        a_C += mvf * tC;
    }

    // Block reduction: warp shuffle -> shared -> per-block partial slot.
    float acc[NACC] = {a_nv, a_np, a_f, a_A, a_B, a_C};
    __shared__ float sh[BLK/32][NACC];
    const int lane = threadIdx.x & 31;
    const int warp = threadIdx.x >> 5;
#pragma unroll
    for (int k = 0; k < NACC; k++) {
        float v = acc[k];
#pragma unroll
        for (int o = 16; o > 0; o >>= 1)
            v += __shfl_down_sync(0xffffffffu, v, o);
        if (lane == 0) sh[warp][k] = v;
    }
    __syncthreads();
    if (threadIdx.x < NACC) {
        float v = 0.0f;
#pragma unroll
        for (int w = 0; w < BLK/32; w++) v += sh[w][threadIdx.x];
        g_part[threadIdx.x][blockIdx.x] = v;
    }

    // Last-block-done: the final block to arrive reduces all partials.
    __shared__ bool is_last;
    __threadfence();
    __syncthreads();
    if (threadIdx.x == 0) {
        unsigned int old = atomicAdd(&g_count, 1u);
        is_last = (old == GRID - 1);
    }
    __syncthreads();
    if (!is_last) return;

    __threadfence();   // ensure we see every block's partials

    // 6 warps reduce the 6 accumulators over all 1920 block partials.
    __shared__ float tot[NACC];
    if (warp < NACC) {
        float v = 0.0f;
        for (int j = lane; j < GRID; j += 32) v += g_part[warp][j];
#pragma unroll
        for (int o = 16; o > 0; o >>= 1)
            v += __shfl_down_sync(0xffffffffu, v, o);
        if (lane == 0) tot[warp] = v;
    }
    __syncthreads();

    if (threadIdx.x == 0) {
        g_count = 0;   // reset for next graph replay

        const float nv      = tot[0];
        const float num_pos = tot[1];
        const float S       = tot[2];
        const float focal = (num_pos == 0.0f) ? S : S / num_pos;
        out[0] = focal + (tot[3] + fminf(tot[4], tot[5])) / nv;
    }
}

extern "C" void kernel_launch(void* const* d_in, const int* in_sizes, int n_in,
                              void* d_out, int out_size) {
    const float* re = (const float*)d_in[0];
    const float* gt = (const float*)d_in[1];
    float* out = (float*)d_out;

    loss_kernel<<<GRID, BLK>>>(re, gt, out);
}